// round 11
// baseline (speedup 1.0000x reference)
#include <cuda_runtime.h>
#include <cuda_bf16.h>
#include <cstdint>
#include <math.h>

#define Bv 64
#define Tv 256
#define Hv 1024
#define Ev 512
#define Av 512
#define Gv 4096   /* 4*H */
#define Cv 2
#define SCAN_BLOCKS 128
#define BH (Bv * Hv)

#define WSLICE 65536               /* 32 rows * 1024 bf16 * 2B */
#define ABUF 32768                 /* 64 rows * 256 bf16 * 2B  */
#define SCAN_SMEM (WSLICE + 4 * ABUF)   /* 196608 */
#define GEMM_SMEM 49152            /* 3-stage: 3*(8K A + 8K B) */

// ---------------- scratch (static device globals; no allocations) ----------------
__device__ __nv_bfloat16 g_A2[(size_t)Tv * Bv * Hv];       // bf16 A
__device__ __nv_bfloat16 g_B2[(size_t)Gv * Hv];            // bf16 B
__device__ __nv_bfloat16 g_WS[(size_t)Gv * Hv];            // per-block swizzled W_hh slices
__device__ __nv_bfloat16 g_HS[2 * 64 * Hv];                // h bf16, double-buffered
__device__ float g_xp  [(size_t)Tv * Bv * Gv];
__device__ float g_seq1[(size_t)Tv * Bv * Hv];
__device__ float g_h   [BH];
__device__ float g_c   [BH];
__device__ float g_m1  [(size_t)Tv * Bv * Av];
__device__ float g_m2  [Bv * Av];
__device__ float g_sc  [Tv * Bv];
__device__ float g_cat [Bv * 2 * Hv];
__device__ float g_nvec[Bv * Hv];
__device__ unsigned g_sdone[4 * 32];   // per-stage monotonic flags, 128B apart

// ---------------- helpers ----------------
__device__ __forceinline__ uint32_t smem_u32(const void* p) {
    uint32_t a;
    asm("{ .reg .u64 t; cvta.to.shared.u64 t, %1; cvt.u32.u64 %0, t; }" : "=r"(a) : "l"(p));
    return a;
}
__device__ __forceinline__ void cp16(uint32_t s, const void* g) {
    asm volatile("cp.async.cg.shared.global [%0], [%1], 16;" :: "r"(s), "l"(g));
}
#define CP_COMMIT() asm volatile("cp.async.commit_group;" ::: "memory")
#define CP_WAIT(n)  asm volatile("cp.async.wait_group %0;" :: "n"(n) : "memory")

__device__ __forceinline__ void ldm_x4(uint32_t* r, uint32_t addr) {
    asm volatile("ldmatrix.sync.aligned.m8n8.x4.shared.b16 {%0,%1,%2,%3}, [%4];"
        : "=r"(r[0]), "=r"(r[1]), "=r"(r[2]), "=r"(r[3]) : "r"(addr));
}
__device__ __forceinline__ void mma16816(float* c, const uint32_t* a, uint32_t b0, uint32_t b1) {
    asm volatile("mma.sync.aligned.m16n8k16.row.col.f32.bf16.bf16.f32 "
        "{%0,%1,%2,%3}, {%4,%5,%6,%7}, {%8,%9}, {%0,%1,%2,%3};"
        : "+f"(c[0]), "+f"(c[1]), "+f"(c[2]), "+f"(c[3])
        : "r"(a[0]), "r"(a[1]), "r"(a[2]), "r"(a[3]), "r"(b0), "r"(b1));
}

union f2u { float2 f; unsigned long long u; };
__device__ __forceinline__ float2 ffma2(float2 a, float2 b, float2 c) {
    f2u A, B, C, D; A.f = a; B.f = b; C.f = c;
    asm("fma.rn.f32x2 %0, %1, %2, %3;" : "=l"(D.u) : "l"(A.u), "l"(B.u), "l"(C.u));
    return D.f;
}
__device__ __forceinline__ float sigmoidf_(float x) { return 1.f / (1.f + expf(-x)); }

// XOR swizzle for 64B-row tiles: conflict-free ldmatrix (validated R5-R10)
__device__ __host__ __forceinline__ uint32_t sw_off(int r, int kq) {
    return (uint32_t)(r * 64 + ((kq ^ ((r >> 1) & 3)) << 4));
}

// ================= mma.sync bf16 GEMM, 3-stage pipeline (validated R8-R10) =================
__global__ __launch_bounds__(256) void mma_gemm(
    const __nv_bfloat16* __restrict__ A2, const __nv_bfloat16* __restrict__ B2,
    float* __restrict__ C, int ldc, int K3,
    const float* __restrict__ bias1, const float* __restrict__ bias2)
{
    extern __shared__ __align__(128) char gsm[];
    const uint32_t uA = smem_u32(gsm);            // 3 x 8192
    const uint32_t uB = uA + 24576;               // 3 x 8192

    const int tid = threadIdx.x, wid = tid >> 5, lid = tid & 31;
    const int wm = wid >> 1, wn = wid & 1;
    const long long mBase = (long long)blockIdx.y * 128;
    const int nBase = blockIdx.x * 128;

    const __nv_bfloat16* Ag = A2 + mBase * (size_t)K3;
    const __nv_bfloat16* Bg = B2 + (size_t)nBase * K3;

    float acc[2][8][4];
#pragma unroll
    for (int i = 0; i < 2; i++)
#pragma unroll
        for (int j = 0; j < 8; j++)
#pragma unroll
            for (int q = 0; q < 4; q++) acc[i][j][q] = 0.f;

    const int NS = K3 / 32;
    const int c0r = (tid * 2) >> 2,     c0q = (tid * 2) & 3;
    const int c1r = (tid * 2 + 1) >> 2, c1q = (tid * 2 + 1) & 3;

    const int aR = ((lid >> 3) & 1) * 8 + (lid & 7);
    const int aQ = (lid >> 4) & 1;
    const int bR = ((lid >> 4) & 1) * 8 + (lid & 7);
    const int bQ = (lid >> 3) & 1;

#pragma unroll
    for (int ps = 0; ps < 2; ps++) {
        const int k0 = ps * 32;
        uint32_t dA = uA + ps * 8192, dB = uB + ps * 8192;
        cp16(dA + sw_off(c0r, c0q), Ag + (size_t)c0r * K3 + k0 + c0q * 8);
        cp16(dA + sw_off(c1r, c1q), Ag + (size_t)c1r * K3 + k0 + c1q * 8);
        cp16(dB + sw_off(c0r, c0q), Bg + (size_t)c0r * K3 + k0 + c0q * 8);
        cp16(dB + sw_off(c1r, c1q), Bg + (size_t)c1r * K3 + k0 + c1q * 8);
        CP_COMMIT();
    }

    int buf = 0, pbuf = 2;
    for (int s = 0; s < NS; s++) {
        if (s + 2 < NS) {
            const int k0 = (s + 2) * 32;
            uint32_t dA = uA + pbuf * 8192, dB = uB + pbuf * 8192;
            cp16(dA + sw_off(c0r, c0q), Ag + (size_t)c0r * K3 + k0 + c0q * 8);
            cp16(dA + sw_off(c1r, c1q), Ag + (size_t)c1r * K3 + k0 + c1q * 8);
            cp16(dB + sw_off(c0r, c0q), Bg + (size_t)c0r * K3 + k0 + c0q * 8);
            cp16(dB + sw_off(c1r, c1q), Bg + (size_t)c1r * K3 + k0 + c1q * 8);
        }
        CP_COMMIT();
        CP_WAIT(2);
        __syncthreads();

        const uint32_t bufA = uA + buf * 8192;
        const uint32_t bufB = uB + buf * 8192;
#pragma unroll
        for (int kk8 = 0; kk8 < 4; kk8 += 2) {
            uint32_t a[2][4];
#pragma unroll
            for (int fm = 0; fm < 2; fm++) {
                int r = wm * 32 + fm * 16 + aR;
                ldm_x4(a[fm], bufA + sw_off(r, kk8 + aQ));
            }
#pragma unroll
            for (int jp = 0; jp < 4; jp++) {
                uint32_t b[4];
                int r = wn * 64 + jp * 16 + bR;
                ldm_x4(b, bufB + sw_off(r, kk8 + bQ));
#pragma unroll
                for (int fm = 0; fm < 2; fm++) {
                    mma16816(acc[fm][2 * jp],     a[fm], b[0], b[1]);
                    mma16816(acc[fm][2 * jp + 1], a[fm], b[2], b[3]);
                }
            }
        }
        __syncthreads();
        buf = (buf == 2) ? 0 : buf + 1;
        pbuf = (pbuf == 2) ? 0 : pbuf + 1;
    }

    const int gid = lid >> 2, tig = lid & 3;
#pragma unroll
    for (int fm = 0; fm < 2; fm++) {
#pragma unroll
        for (int j = 0; j < 8; j++) {
            int n = nBase + wn * 64 + j * 8 + tig * 2;
            float b0 = 0.f, b1 = 0.f;
            if (bias1) { b0 = bias1[n]; b1 = bias1[n + 1]; }
            if (bias2) { b0 += bias2[n]; b1 += bias2[n + 1]; }
            long long m0 = mBase + wm * 32 + fm * 16 + gid;
            float* r0 = C + m0 * (long long)ldc + n;
            r0[0] = acc[fm][j][0] + b0;
            r0[1] = acc[fm][j][1] + b1;
            float* r1 = r0 + 8LL * ldc;
            r1[0] = acc[fm][j][2] + b0;
            r1[1] = acc[fm][j][3] + b1;
        }
    }
}

// ---------------- packing kernels ----------------
__global__ void pack_B(const float* __restrict__ W, int N, int K) {
    int i = blockIdx.x * blockDim.x + threadIdx.x;
    if (i >= N * K) return;
    g_B2[(size_t)i] = __float2bfloat16(W[i]);
}

// scan weights: per-block (128 blocks x 8 units) pre-swizzled smem image (R8 layout)
__global__ void pack_WS(const float* __restrict__ W) {
    int i = blockIdx.x * blockDim.x + threadIdx.x;   // over Gv*Hv
    if (i >= Gv * Hv) return;
    int n = i >> 10, k = i & 1023;
    __nv_bfloat16 hi = __float2bfloat16(W[i]);
    int g = n >> 10, bi = (n & 1023) >> 3, j = n & 7;
    int r = g * 8 + j;
    char* base = (char*)g_WS + (size_t)bi * WSLICE;
    *(__nv_bfloat16*)(base + (size_t)(k >> 5) * 2048
                      + sw_off(r, (k >> 3) & 3) + (k & 7) * 2) = hi;
}

// embedding gather into A2 bf16, row stride Ev
__global__ void gather_pack(const int* __restrict__ x, const float* __restrict__ ew) {
    int m = blockIdx.x;            // t*B + b
    int b = m & 63, t = m >> 6;
    int row = x[b * Tv + t];
    const float* src = ew + (size_t)row * Ev;
    __nv_bfloat16* dst = g_A2 + (size_t)m * Ev;
    for (int k = threadIdx.x; k < Ev; k += blockDim.x)
        dst[k] = __float2bfloat16(src[k]);
}

__global__ void zero_state() {
    int i = blockIdx.x * blockDim.x + threadIdx.x;
    if (i < BH) { g_h[i] = 0.f; g_c[i] = 0.f; }
    if (i < 4 * 32) g_sdone[i] = 0u;
}

// ---------------- persistent LSTM scan, per-stage dataflow flags ----------------
// 128 blocks x 256 threads (8 warps: 4m x 2n). Block bi owns units u0=bi*8 -> 32 gate rows.
// W slice (64KB) smem-resident. Per step: Y[64x32] = Hbf16[64x1024] . Wslice^T,
// 4 stages of BK=256, 4-buffer cp.async pipeline. NO global barrier: stage s of step t
// gates its cp.async on g_sdone[s*32] >= 32t (producers = blocks 32s..32s+31, which
// incremented after writing h of step t-1). tid0-only polling; monotonic counters.
__global__ __launch_bounds__(256) void lstm_scan_mma(
    const __nv_bfloat16* __restrict__ WS,
    const float* __restrict__ xp,
    float* __restrict__ seq,            // nullable
    __nv_bfloat16* __restrict__ a2)     // nullable (bf16 seq out, stride Hv)
{
    extern __shared__ __align__(128) char sm[];
    const int tid = threadIdx.x, wid = tid >> 5, lid = tid & 31;
    const int wm = wid >> 1, wn = wid & 1;
    const int bi = blockIdx.x, u0 = bi * 8;
    const uint32_t sW = smem_u32(sm);
    const uint32_t sA = sW + WSLICE;
    float* Cs = (float*)(sm + WSLICE);   // overlays A buffers (disjoint in time)

    const int aR = ((lid >> 3) & 1) * 8 + (lid & 7);
    const int aQ = (lid >> 4) & 1;
    const int bR = ((lid >> 4) & 1) * 8 + (lid & 7);
    const int bQ = (lid >> 3) & 1;
    const int gid = lid >> 2, tig = lid & 3;
    const int myFlag = (bi >> 5) * 32;    // this block produces h columns of stage bi>>5

    // load W slice (64KB) once
    {
        const char* wg = (const char*)WS + (size_t)bi * WSLICE;
        for (int i = tid; i < WSLICE / 16; i += 256)
            cp16(sW + (uint32_t)(i * 16), wg + (size_t)i * 16);
        CP_COMMIT(); CP_WAIT(0);
        __syncthreads();
    }

    const int pb0 = tid >> 3, pj = tid & 7;

    // xp prefetch for t=0
    float xv[2][4];
#pragma unroll
    for (int q = 0; q < 2; q++) {
        int b = pb0 + q * 32;
        const float* xr = xp + (size_t)b * Gv + u0 + pj;
#pragma unroll
        for (int g = 0; g < 4; g++) xv[q][g] = __ldg(xr + g * Hv);
    }

    for (int t = 0; t < Tv; t++) {
        if (t > 0) {
            const __nv_bfloat16* HS = g_HS + (size_t)(t & 1) * (64 * Hv);
            const unsigned need = 32u * (unsigned)t;
            float acc[2][4];
#pragma unroll
            for (int j = 0; j < 2; j++)
#pragma unroll
                for (int q = 0; q < 4; q++) acc[j][q] = 0.f;

            // gated prefetch of stages 0..2 (BK=256, 32KB each; 8 cp16/thread)
#pragma unroll
            for (int s = 0; s < 3; s++) {
                if (tid == 0)
                    while (*(volatile unsigned*)&g_sdone[s * 32] < need) { }
                __syncthreads();
                int k0 = s * 256;
#pragma unroll
                for (int q = 0; q < 8; q++) {
                    int id = tid + q * 256;
                    int r = id >> 5, c16 = id & 31;
                    cp16(sA + s * ABUF + (c16 >> 2) * 4096 + sw_off(r, c16 & 3),
                         HS + (size_t)r * Hv + k0 + c16 * 8);
                }
                CP_COMMIT();
            }

#pragma unroll 1
            for (int s = 0; s < 4; s++) {
                CP_WAIT(2);
                __syncthreads();
                const uint32_t bufA = sA + (s & 3) * ABUF;
                const uint32_t bufW = sW + (uint32_t)s * 16384;
#pragma unroll
                for (int sub = 0; sub < 8; sub++) {
#pragma unroll
                    for (int kk8 = 0; kk8 < 4; kk8 += 2) {
                        uint32_t a[4], b[4];
                        ldm_x4(a, bufA + sub * 4096 + sw_off(wm * 16 + aR, kk8 + aQ));
                        ldm_x4(b, bufW + sub * 2048 + sw_off(wn * 16 + bR, kk8 + bQ));
                        mma16816(acc[0], a, b[0], b[1]);
                        mma16816(acc[1], a, b[2], b[3]);
                    }
                }
                if (s + 3 < 4) {          // only s==0: gated refill of stage 3
                    if (tid == 0)
                        while (*(volatile unsigned*)&g_sdone[3 * 32] < need) { }
                    __syncthreads();
                    int k0 = 3 * 256;
                    uint32_t d = sA + 3 * ABUF;
#pragma unroll
                    for (int q = 0; q < 8; q++) {
                        int id = tid + q * 256;
                        int r = id >> 5, c16 = id & 31;
                        cp16(d + (c16 >> 2) * 4096 + sw_off(r, c16 & 3),
                             HS + (size_t)r * Hv + k0 + c16 * 8);
                    }
                }
                CP_COMMIT();
            }
            __syncthreads();             // A buffers idle -> Cs overlay

#pragma unroll
            for (int j = 0; j < 2; j++) {
                int n = wn * 16 + j * 8 + tig * 2;
                int b0 = wm * 16 + gid;
                Cs[b0 * 33 + n]           = acc[j][0];
                Cs[b0 * 33 + n + 1]       = acc[j][1];
                Cs[(b0 + 8) * 33 + n]     = acc[j][2];
                Cs[(b0 + 8) * 33 + n + 1] = acc[j][3];
            }
            __syncthreads();
        }

        __nv_bfloat16* HSw = g_HS + (size_t)((t + 1) & 1) * (64 * Hv);
#pragma unroll
        for (int q = 0; q < 2; q++) {
            int b = pb0 + q * 32;
            float gi = xv[q][0], gf = xv[q][1], gg = xv[q][2], go = xv[q][3];
            if (t > 0) {
                gi += Cs[b * 33 + pj];
                gf += Cs[b * 33 + 8 + pj];
                gg += Cs[b * 33 + 16 + pj];
                go += Cs[b * 33 + 24 + pj];
            }
            int ci = b * Hv + u0 + pj;
            float c = sigmoidf_(gf) * g_c[ci] + sigmoidf_(gi) * tanhf(gg);
            float h = sigmoidf_(go) * tanhf(c);
            g_c[ci] = c;
            __nv_bfloat16 hh = __float2bfloat16(h);
            HSw[(size_t)b * Hv + u0 + pj] = hh;
            if (seq) seq[((size_t)(t * Bv + b)) * Hv + u0 + pj] = h;
            if (a2) a2[((size_t)(t * Bv + b)) * Hv + u0 + pj] = hh;
            if (t == Tv - 1) g_h[ci] = h;
        }

        if (t < Tv - 1) {
            // xp prefetch for t+1 (independent of h) overlaps the signal path
#pragma unroll
            for (int q = 0; q < 2; q++) {
                int b = pb0 + q * 32;
                const float* xr = xp + ((size_t)((t + 1) * Bv + b)) * Gv + u0 + pj;
#pragma unroll
                for (int g = 0; g < 4; g++) xv[q][g] = __ldg(xr + g * Hv);
            }
            __threadfence();          // h stores visible in L2 before the flag
            __syncthreads();          // whole block's stores fenced
            if (tid == 0) atomicAdd(&g_sdone[myFlag], 1u);
            // NO wait here — the wait is the gated prefetch of the next step
        }
    }
}

// ---------------- small FFMA2 sgemm (tiny GEMMs: m2, n_vec) ----------------
#define BKt 16
__global__ __launch_bounds__(128) void sgemm(
    const float* __restrict__ A, int lda,
    const float* __restrict__ B, int ldb,
    float* __restrict__ C, int ldc,
    int K, const float* __restrict__ bias1, int act)
{
    __shared__ __align__(16) float As[BKt][64 + 4];
    __shared__ __align__(16) float Bs[BKt][64 + 4];
    const int tid = threadIdx.x;
    const int nBase = blockIdx.x * 64;
    const long long mBase = (long long)blockIdx.y * 64;
    const int ty = tid >> 4, tx = tid & 15;

    float2 acc[8][2];
#pragma unroll
    for (int i = 0; i < 8; i++) { acc[i][0] = make_float2(0.f, 0.f); acc[i][1] = make_float2(0.f, 0.f); }

    for (int k0 = 0; k0 < K; k0 += BKt) {
#pragma unroll
        for (int i = 0; i < 2; i++) {
            int f = i * 128 + tid;
            int m = f >> 2, kq = f & 3;
            float4 va = *(const float4*)&A[(mBase + m) * (long long)lda + k0 + kq * 4];
            As[kq * 4 + 0][m] = va.x; As[kq * 4 + 1][m] = va.y;
            As[kq * 4 + 2][m] = va.z; As[kq * 4 + 3][m] = va.w;
            float4 vb = *(const float4*)&B[(long long)(nBase + m) * ldb + k0 + kq * 4];
            Bs[kq * 4 + 0][m] = vb.x; Bs[kq * 4 + 1][m] = vb.y;
            Bs[kq * 4 + 2][m] = vb.z; Bs[kq * 4 + 3][m] = vb.w;
        }
        __syncthreads();
#pragma unroll
        for (int kk = 0; kk < BKt; kk++) {
            float4 a0 = *(const float4*)&As[kk][ty * 8];
            float4 a1 = *(const float4*)&As[kk][ty * 8 + 4];
            float4 b4 = *(const float4*)&Bs[kk][tx * 4];
            float2 b01 = make_float2(b4.x, b4.y);
            float2 b23 = make_float2(b4.z, b4.w);
            float av[8] = {a0.x, a0.y, a0.z, a0.w, a1.x, a1.y, a1.z, a1.w};
#pragma unroll
            for (int i = 0; i < 8; i++) {
                float2 ad = make_float2(av[i], av[i]);
                acc[i][0] = ffma2(ad, b01, acc[i][0]);
                acc[i][1] = ffma2(ad, b23, acc[i][1]);
            }
        }
        __syncthreads();
    }

    float4 bb = make_float4(0.f, 0.f, 0.f, 0.f);
    if (bias1) bb = *(const float4*)&bias1[nBase + tx * 4];
#pragma unroll
    for (int i = 0; i < 8; i++) {
        long long m = mBase + ty * 8 + i;
        float4 r = make_float4(acc[i][0].x + bb.x, acc[i][0].y + bb.y,
                               acc[i][1].x + bb.z, acc[i][1].y + bb.w);
        if (act == 1) { r.x = tanhf(r.x); r.y = tanhf(r.y); r.z = tanhf(r.z); r.w = tanhf(r.w); }
        *(float4*)&C[m * (long long)ldc + nBase + tx * 4] = r;
    }
}

// ---------------- attention tail ----------------
__global__ void scores_k(const float* __restrict__ v) {
    int warp = (blockIdx.x * blockDim.x + threadIdx.x) >> 5;
    int lane = threadIdx.x & 31;
    if (warp >= Tv * Bv) return;
    int b = warp & 63;
    const float* m1 = g_m1 + (size_t)warp * Av;
    const float* m2 = g_m2 + b * Av;
    float s = 0.f;
    for (int a = lane; a < Av; a += 32) s += tanhf(m1[a] + m2[a]) * v[a];
#pragma unroll
    for (int o = 16; o; o >>= 1) s += __shfl_xor_sync(0xffffffffu, s, o);
    if (!lane) g_sc[warp] = s;
}

__global__ void softmax_k() {
    int b = blockIdx.x;
    int t = threadIdx.x;
    __shared__ float red[Tv];
    float val = g_sc[t * Bv + b];
    red[t] = val; __syncthreads();
    for (int o = 128; o; o >>= 1) { if (t < o) red[t] = fmaxf(red[t], red[t + o]); __syncthreads(); }
    float mx = red[0]; __syncthreads();
    float e = expf(val - mx);
    red[t] = e; __syncthreads();
    for (int o = 128; o; o >>= 1) { if (t < o) red[t] += red[t + o]; __syncthreads(); }
    g_sc[t * Bv + b] = e / red[0];
}

// (b, h-range of 128) grid
__global__ void context_k() {
    int b = blockIdx.x;
    int h0 = blockIdx.y * 128;
    __shared__ float at[Tv];
    for (int t = threadIdx.x; t < Tv; t += blockDim.x) at[t] = g_sc[t * Bv + b];
    __syncthreads();
    int h = h0 + threadIdx.x;
    float s = 0.f;
#pragma unroll 4
    for (int t = 0; t < Tv; t++)
        s += g_seq1[((size_t)(t * Bv + b)) * Hv + h] * at[t];
    g_cat[b * 2 * Hv + h] = s;
    g_cat[b * 2 * Hv + Hv + h] = g_h[b * Hv + h];
}

__global__ void logit_k(const float* __restrict__ ow, const float* __restrict__ ob,
                        float* __restrict__ out) {
    int idx = blockIdx.x;
    int b = idx >> 1, c = idx & 1;
    int lane = threadIdx.x;
    float s = 0.f;
    for (int k = lane; k < Hv; k += 32) s += g_nvec[b * Hv + k] * ow[c * Hv + k];
#pragma unroll
    for (int o = 16; o; o >>= 1) s += __shfl_xor_sync(0xffffffffu, s, o);
    if (!lane) out[idx] = s + ob[c];
}

// ---------------- host orchestration ----------------
extern "C" void kernel_launch(void* const* d_in, const int* in_sizes, int n_in,
                              void* d_out, int out_size) {
    const int*   x      = (const int*)d_in[0];
    const float* embed_w= (const float*)d_in[1];
    const float* w_ih0  = (const float*)d_in[2];
    const float* w_hh0  = (const float*)d_in[3];
    const float* b_ih0  = (const float*)d_in[4];
    const float* b_hh0  = (const float*)d_in[5];
    const float* w_ih1  = (const float*)d_in[6];
    const float* w_hh1  = (const float*)d_in[7];
    const float* b_ih1  = (const float*)d_in[8];
    const float* b_hh1  = (const float*)d_in[9];
    const float* m1_w   = (const float*)d_in[10];
    const float* m1_b   = (const float*)d_in[11];
    const float* m2_w   = (const float*)d_in[12];
    const float* m2_b   = (const float*)d_in[13];
    const float* vv     = (const float*)d_in[14];
    const float* n_w    = (const float*)d_in[15];
    const float* n_b    = (const float*)d_in[16];
    const float* out_w  = (const float*)d_in[17];
    const float* out_b  = (const float*)d_in[18];
    float* out = (float*)d_out;

    cudaFuncSetAttribute(lstm_scan_mma, cudaFuncAttributeMaxDynamicSharedMemorySize, SCAN_SMEM);
    cudaFuncSetAttribute(mma_gemm, cudaFuncAttributeMaxDynamicSharedMemorySize, GEMM_SMEM);

    __nv_bfloat16 *p_A2, *p_B2, *p_WS;
    float *p_xp, *p_seq1, *p_h, *p_m1, *p_m2, *p_cat, *p_nvec;
    cudaGetSymbolAddress((void**)&p_A2,   g_A2);
    cudaGetSymbolAddress((void**)&p_B2,   g_B2);
    cudaGetSymbolAddress((void**)&p_WS,   g_WS);
    cudaGetSymbolAddress((void**)&p_xp,   g_xp);
    cudaGetSymbolAddress((void**)&p_seq1, g_seq1);
    cudaGetSymbolAddress((void**)&p_h,    g_h);
    cudaGetSymbolAddress((void**)&p_m1,   g_m1);
    cudaGetSymbolAddress((void**)&p_m2,   g_m2);
    cudaGetSymbolAddress((void**)&p_cat,  g_cat);
    cudaGetSymbolAddress((void**)&p_nvec, g_nvec);

    // ---- layer 0 ----
    gather_pack<<<Tv * Bv, 128>>>(x, embed_w);
    pack_B<<<(Gv * Ev + 255) / 256, 256>>>(w_ih0, Gv, Ev);
    mma_gemm<<<dim3(Gv / 128, (Tv * Bv) / 128), 256, GEMM_SMEM>>>(p_A2, p_B2, p_xp, Gv,
                                                                  Ev, b_ih0, b_hh0);
    pack_WS<<<(Gv * Hv + 255) / 256, 256>>>(w_hh0);
    zero_state<<<256, 256>>>();
    lstm_scan_mma<<<SCAN_BLOCKS, 256, SCAN_SMEM>>>(p_WS, p_xp, nullptr, p_A2);

    // ---- layer 1 ----
    pack_B<<<(Gv * Hv + 255) / 256, 256>>>(w_ih1, Gv, Hv);
    mma_gemm<<<dim3(Gv / 128, (Tv * Bv) / 128), 256, GEMM_SMEM>>>(p_A2, p_B2, p_xp, Gv,
                                                                  Hv, b_ih1, b_hh1);
    pack_WS<<<(Gv * Hv + 255) / 256, 256>>>(w_hh1);
    zero_state<<<256, 256>>>();
    lstm_scan_mma<<<SCAN_BLOCKS, 256, SCAN_SMEM>>>(p_WS, p_xp, p_seq1, p_A2);

    // ---- attention ----
    pack_B<<<(Av * Hv + 255) / 256, 256>>>(m1_w, Av, Hv);
    mma_gemm<<<dim3(Av / 128, (Tv * Bv) / 128), 256, GEMM_SMEM>>>(p_A2, p_B2, p_m1, Av,
                                                                  Hv, m1_b, nullptr);
    sgemm<<<dim3(Av / 64, 1), 128>>>(p_h, Hv, m2_w, Hv, p_m2, Av, Hv, m2_b, 0);
    scores_k<<<(Tv * Bv * 32) / 256, 256>>>(vv);
    softmax_k<<<Bv, Tv>>>();
    context_k<<<dim3(Bv, Hv / 128), 128>>>();
    sgemm<<<dim3(Hv / 64, 1), 128>>>(p_cat, 2 * Hv, n_w, 2 * Hv, p_nvec, Hv, 2 * Hv, n_b, 1);
    logit_k<<<Bv * Cv, 32>>>(out_w, out_b, out);
}

// round 12
// speedup vs baseline: 1.2202x; 1.2202x over previous
#include <cuda_runtime.h>
#include <cuda_bf16.h>
#include <cstdint>
#include <math.h>

#define Bv 64
#define Tv 256
#define Hv 1024
#define Ev 512
#define Av 512
#define Gv 4096   /* 4*H */
#define Cv 2
#define SCAN_BLOCKS 128
#define BH (Bv * Hv)

#define WSLICE 65536               /* 32 rows * 1024 bf16 * 2B */
#define ABUF 32768                 /* 64 rows * 256 bf16 * 2B  */
#define SCAN_SMEM (WSLICE + 4 * ABUF)   /* 196608 */
#define GEMM_SMEM 49152            /* 3-stage: 3*(8K A + 8K B) */

// ---------------- scratch (static device globals; no allocations) ----------------
__device__ __nv_bfloat16 g_A2[(size_t)Tv * Bv * Hv];       // bf16 A
__device__ __nv_bfloat16 g_B2[(size_t)Gv * Hv];            // bf16 B
__device__ __nv_bfloat16 g_WS[(size_t)Gv * Hv];            // per-block swizzled W_hh slices
__device__ __nv_bfloat16 g_HS[2 * 64 * Hv];                // h bf16, double-buffered
__device__ float g_xp  [(size_t)Tv * Bv * Gv];
__device__ float g_seq1[(size_t)Tv * Bv * Hv];
__device__ float g_h   [BH];
__device__ float g_m1  [(size_t)Tv * Bv * Av];
__device__ float g_m2  [Bv * Av];
__device__ float g_sc  [Tv * Bv];
__device__ float g_cat [Bv * 2 * Hv];
__device__ float g_nvec[Bv * Hv];
__device__ unsigned g_barrier;

// ---------------- helpers ----------------
__device__ __forceinline__ uint32_t smem_u32(const void* p) {
    uint32_t a;
    asm("{ .reg .u64 t; cvta.to.shared.u64 t, %1; cvt.u32.u64 %0, t; }" : "=r"(a) : "l"(p));
    return a;
}
__device__ __forceinline__ void cp16(uint32_t s, const void* g) {
    asm volatile("cp.async.cg.shared.global [%0], [%1], 16;" :: "r"(s), "l"(g));
}
#define CP_COMMIT() asm volatile("cp.async.commit_group;" ::: "memory")
#define CP_WAIT(n)  asm volatile("cp.async.wait_group %0;" :: "n"(n) : "memory")

__device__ __forceinline__ void ldm_x4(uint32_t* r, uint32_t addr) {
    asm volatile("ldmatrix.sync.aligned.m8n8.x4.shared.b16 {%0,%1,%2,%3}, [%4];"
        : "=r"(r[0]), "=r"(r[1]), "=r"(r[2]), "=r"(r[3]) : "r"(addr));
}
__device__ __forceinline__ void mma16816(float* c, const uint32_t* a, uint32_t b0, uint32_t b1) {
    asm volatile("mma.sync.aligned.m16n8k16.row.col.f32.bf16.bf16.f32 "
        "{%0,%1,%2,%3}, {%4,%5,%6,%7}, {%8,%9}, {%0,%1,%2,%3};"
        : "+f"(c[0]), "+f"(c[1]), "+f"(c[2]), "+f"(c[3])
        : "r"(a[0]), "r"(a[1]), "r"(a[2]), "r"(a[3]), "r"(b0), "r"(b1));
}

union f2u { float2 f; unsigned long long u; };
__device__ __forceinline__ float2 ffma2(float2 a, float2 b, float2 c) {
    f2u A, B, C, D; A.f = a; B.f = b; C.f = c;
    asm("fma.rn.f32x2 %0, %1, %2, %3;" : "=l"(D.u) : "l"(A.u), "l"(B.u), "l"(C.u));
    return D.f;
}

// fast transcendentals: __expf = ex2.approx (rel err ~2^-21), near-exact at our scale
__device__ __forceinline__ float sigmoidf_(float x) {
    return __fdividef(1.f, 1.f + __expf(-x));
}
__device__ __forceinline__ float tanhf_(float x) {
    x = fminf(15.f, fmaxf(-15.f, x));
    float e = __expf(2.f * x);
    return __fdividef(e - 1.f, e + 1.f);
}

// XOR swizzle for 64B-row tiles: conflict-free ldmatrix (validated R5-R11)
__device__ __host__ __forceinline__ uint32_t sw_off(int r, int kq) {
    return (uint32_t)(r * 64 + ((kq ^ ((r >> 1) & 3)) << 4));
}

// ================= mma.sync bf16 GEMM, 3-stage pipeline (validated R8-R11) =================
__global__ __launch_bounds__(256) void mma_gemm(
    const __nv_bfloat16* __restrict__ A2, const __nv_bfloat16* __restrict__ B2,
    float* __restrict__ C, int ldc, int K3,
    const float* __restrict__ bias1, const float* __restrict__ bias2)
{
    extern __shared__ __align__(128) char gsm[];
    const uint32_t uA = smem_u32(gsm);            // 3 x 8192
    const uint32_t uB = uA + 24576;               // 3 x 8192

    const int tid = threadIdx.x, wid = tid >> 5, lid = tid & 31;
    const int wm = wid >> 1, wn = wid & 1;
    const long long mBase = (long long)blockIdx.y * 128;
    const int nBase = blockIdx.x * 128;

    const __nv_bfloat16* Ag = A2 + mBase * (size_t)K3;
    const __nv_bfloat16* Bg = B2 + (size_t)nBase * K3;

    float acc[2][8][4];
#pragma unroll
    for (int i = 0; i < 2; i++)
#pragma unroll
        for (int j = 0; j < 8; j++)
#pragma unroll
            for (int q = 0; q < 4; q++) acc[i][j][q] = 0.f;

    const int NS = K3 / 32;
    const int c0r = (tid * 2) >> 2,     c0q = (tid * 2) & 3;
    const int c1r = (tid * 2 + 1) >> 2, c1q = (tid * 2 + 1) & 3;

    const int aR = ((lid >> 3) & 1) * 8 + (lid & 7);
    const int aQ = (lid >> 4) & 1;
    const int bR = ((lid >> 4) & 1) * 8 + (lid & 7);
    const int bQ = (lid >> 3) & 1;

#pragma unroll
    for (int ps = 0; ps < 2; ps++) {
        const int k0 = ps * 32;
        uint32_t dA = uA + ps * 8192, dB = uB + ps * 8192;
        cp16(dA + sw_off(c0r, c0q), Ag + (size_t)c0r * K3 + k0 + c0q * 8);
        cp16(dA + sw_off(c1r, c1q), Ag + (size_t)c1r * K3 + k0 + c1q * 8);
        cp16(dB + sw_off(c0r, c0q), Bg + (size_t)c0r * K3 + k0 + c0q * 8);
        cp16(dB + sw_off(c1r, c1q), Bg + (size_t)c1r * K3 + k0 + c1q * 8);
        CP_COMMIT();
    }

    int buf = 0, pbuf = 2;
    for (int s = 0; s < NS; s++) {
        if (s + 2 < NS) {
            const int k0 = (s + 2) * 32;
            uint32_t dA = uA + pbuf * 8192, dB = uB + pbuf * 8192;
            cp16(dA + sw_off(c0r, c0q), Ag + (size_t)c0r * K3 + k0 + c0q * 8);
            cp16(dA + sw_off(c1r, c1q), Ag + (size_t)c1r * K3 + k0 + c1q * 8);
            cp16(dB + sw_off(c0r, c0q), Bg + (size_t)c0r * K3 + k0 + c0q * 8);
            cp16(dB + sw_off(c1r, c1q), Bg + (size_t)c1r * K3 + k0 + c1q * 8);
        }
        CP_COMMIT();
        CP_WAIT(2);
        __syncthreads();

        const uint32_t bufA = uA + buf * 8192;
        const uint32_t bufB = uB + buf * 8192;
#pragma unroll
        for (int kk8 = 0; kk8 < 4; kk8 += 2) {
            uint32_t a[2][4];
#pragma unroll
            for (int fm = 0; fm < 2; fm++) {
                int r = wm * 32 + fm * 16 + aR;
                ldm_x4(a[fm], bufA + sw_off(r, kk8 + aQ));
            }
#pragma unroll
            for (int jp = 0; jp < 4; jp++) {
                uint32_t b[4];
                int r = wn * 64 + jp * 16 + bR;
                ldm_x4(b, bufB + sw_off(r, kk8 + bQ));
#pragma unroll
                for (int fm = 0; fm < 2; fm++) {
                    mma16816(acc[fm][2 * jp],     a[fm], b[0], b[1]);
                    mma16816(acc[fm][2 * jp + 1], a[fm], b[2], b[3]);
                }
            }
        }
        __syncthreads();
        buf = (buf == 2) ? 0 : buf + 1;
        pbuf = (pbuf == 2) ? 0 : pbuf + 1;
    }

    const int gid = lid >> 2, tig = lid & 3;
#pragma unroll
    for (int fm = 0; fm < 2; fm++) {
#pragma unroll
        for (int j = 0; j < 8; j++) {
            int n = nBase + wn * 64 + j * 8 + tig * 2;
            float b0 = 0.f, b1 = 0.f;
            if (bias1) { b0 = bias1[n]; b1 = bias1[n + 1]; }
            if (bias2) { b0 += bias2[n]; b1 += bias2[n + 1]; }
            long long m0 = mBase + wm * 32 + fm * 16 + gid;
            float* r0 = C + m0 * (long long)ldc + n;
            r0[0] = acc[fm][j][0] + b0;
            r0[1] = acc[fm][j][1] + b1;
            float* r1 = r0 + 8LL * ldc;
            r1[0] = acc[fm][j][2] + b0;
            r1[1] = acc[fm][j][3] + b1;
        }
    }
}

// ---------------- packing kernels ----------------
__global__ void pack_B(const float* __restrict__ W, int N, int K) {
    int i = blockIdx.x * blockDim.x + threadIdx.x;
    if (i >= N * K) return;
    g_B2[(size_t)i] = __float2bfloat16(W[i]);
}

// scan weights: per-block (128 blocks x 8 units) pre-swizzled smem image (R8 layout)
__global__ void pack_WS(const float* __restrict__ W) {
    int i = blockIdx.x * blockDim.x + threadIdx.x;   // over Gv*Hv
    if (i >= Gv * Hv) return;
    int n = i >> 10, k = i & 1023;
    __nv_bfloat16 hi = __float2bfloat16(W[i]);
    int g = n >> 10, bi = (n & 1023) >> 3, j = n & 7;
    int r = g * 8 + j;
    char* base = (char*)g_WS + (size_t)bi * WSLICE;
    *(__nv_bfloat16*)(base + (size_t)(k >> 5) * 2048
                      + sw_off(r, (k >> 3) & 3) + (k & 7) * 2) = hi;
}

// embedding gather into A2 bf16, row stride Ev
__global__ void gather_pack(const int* __restrict__ x, const float* __restrict__ ew) {
    int m = blockIdx.x;            // t*B + b
    int b = m & 63, t = m >> 6;
    int row = x[b * Tv + t];
    const float* src = ew + (size_t)row * Ev;
    __nv_bfloat16* dst = g_A2 + (size_t)m * Ev;
    for (int k = threadIdx.x; k < Ev; k += blockDim.x)
        dst[k] = __float2bfloat16(src[k]);
}

__global__ void zero_state() {
    int i = blockIdx.x * blockDim.x + threadIdx.x;
    if (i < BH) g_h[i] = 0.f;
    if (i == 0) g_barrier = 0u;
}

// ---------------- persistent LSTM scan on tensor cores (R10 structure) ----------------
// 128 blocks x 256 threads. Block bi owns units u0=bi*8 -> 32 gate rows. W slice (64KB)
// smem-resident. 4 stages of BK=256, 4-buffer cp.async pipeline; ONE grid barrier/step
// (release-atomic arrival, acquire poll); c held in REGISTERS; fast transcendentals.
__global__ __launch_bounds__(256) void lstm_scan_mma(
    const __nv_bfloat16* __restrict__ WS,
    const float* __restrict__ xp,
    float* __restrict__ seq,            // nullable
    __nv_bfloat16* __restrict__ a2)     // nullable (bf16 seq out, stride Hv)
{
    extern __shared__ __align__(128) char sm[];
    const int tid = threadIdx.x, wid = tid >> 5, lid = tid & 31;
    const int wm = wid >> 1, wn = wid & 1;
    const int bi = blockIdx.x, u0 = bi * 8;
    const uint32_t sW = smem_u32(sm);
    const uint32_t sA = sW + WSLICE;
    float* Cs = (float*)(sm + WSLICE);   // overlays A buffers (disjoint in time)

    const int aR = ((lid >> 3) & 1) * 8 + (lid & 7);
    const int aQ = (lid >> 4) & 1;
    const int bR = ((lid >> 4) & 1) * 8 + (lid & 7);
    const int bQ = (lid >> 3) & 1;
    const int gid = lid >> 2, tig = lid & 3;

    // load W slice (64KB) once
    {
        const char* wg = (const char*)WS + (size_t)bi * WSLICE;
        for (int i = tid; i < WSLICE / 16; i += 256)
            cp16(sW + (uint32_t)(i * 16), wg + (size_t)i * 16);
        CP_COMMIT(); CP_WAIT(0);
        __syncthreads();
    }

    const int pb0 = tid >> 3, pj = tid & 7;

    // LSTM cell state lives in registers (mapping constant across t)
    float cReg[2] = {0.f, 0.f};

    // xp prefetch for t=0
    float xv[2][4];
#pragma unroll
    for (int q = 0; q < 2; q++) {
        int b = pb0 + q * 32;
        const float* xr = xp + (size_t)b * Gv + u0 + pj;
#pragma unroll
        for (int g = 0; g < 4; g++) xv[q][g] = __ldg(xr + g * Hv);
    }

    for (int t = 0; t < Tv; t++) {
        if (t > 0) {
            const __nv_bfloat16* HS = g_HS + (size_t)(t & 1) * (64 * Hv);
            float acc[2][4];
#pragma unroll
            for (int j = 0; j < 2; j++)
#pragma unroll
                for (int q = 0; q < 4; q++) acc[j][q] = 0.f;

            // prefetch stages 0..2 (BK=256, 32KB each; 8 cp16/thread)
#pragma unroll
            for (int s = 0; s < 3; s++) {
                int k0 = s * 256;
#pragma unroll
                for (int q = 0; q < 8; q++) {
                    int id = tid + q * 256;
                    int r = id >> 5, c16 = id & 31;
                    cp16(sA + s * ABUF + (c16 >> 2) * 4096 + sw_off(r, c16 & 3),
                         HS + (size_t)r * Hv + k0 + c16 * 8);
                }
                CP_COMMIT();
            }

#pragma unroll 1
            for (int s = 0; s < 4; s++) {
                CP_WAIT(2);
                __syncthreads();
                const uint32_t bufA = sA + (s & 3) * ABUF;
                const uint32_t bufW = sW + (uint32_t)s * 16384;
#pragma unroll
                for (int sub = 0; sub < 8; sub++) {
#pragma unroll
                    for (int kk8 = 0; kk8 < 4; kk8 += 2) {
                        uint32_t a[4], b[4];
                        ldm_x4(a, bufA + sub * 4096 + sw_off(wm * 16 + aR, kk8 + aQ));
                        ldm_x4(b, bufW + sub * 2048 + sw_off(wn * 16 + bR, kk8 + bQ));
                        mma16816(acc[0], a, b[0], b[1]);
                        mma16816(acc[1], a, b[2], b[3]);
                    }
                }
                if (s + 3 < 4) {
                    int k0 = (s + 3) * 256;
                    uint32_t d = sA + ((s + 3) & 3) * ABUF;
#pragma unroll
                    for (int q = 0; q < 8; q++) {
                        int id = tid + q * 256;
                        int r = id >> 5, c16 = id & 31;
                        cp16(d + (c16 >> 2) * 4096 + sw_off(r, c16 & 3),
                             HS + (size_t)r * Hv + k0 + c16 * 8);
                    }
                }
                CP_COMMIT();
            }
            __syncthreads();             // A buffers idle -> Cs overlay

#pragma unroll
            for (int j = 0; j < 2; j++) {
                int n = wn * 16 + j * 8 + tig * 2;
                int b0 = wm * 16 + gid;
                Cs[b0 * 33 + n]           = acc[j][0];
                Cs[b0 * 33 + n + 1]       = acc[j][1];
                Cs[(b0 + 8) * 33 + n]     = acc[j][2];
                Cs[(b0 + 8) * 33 + n + 1] = acc[j][3];
            }
            __syncthreads();
        }

        __nv_bfloat16* HSw = g_HS + (size_t)((t + 1) & 1) * (64 * Hv);
#pragma unroll
        for (int q = 0; q < 2; q++) {
            int b = pb0 + q * 32;
            float gi = xv[q][0], gf = xv[q][1], gg = xv[q][2], go = xv[q][3];
            if (t > 0) {
                gi += Cs[b * 33 + pj];
                gf += Cs[b * 33 + 8 + pj];
                gg += Cs[b * 33 + 16 + pj];
                go += Cs[b * 33 + 24 + pj];
            }
            float c = sigmoidf_(gf) * cReg[q] + sigmoidf_(gi) * tanhf_(gg);
            float h = sigmoidf_(go) * tanhf_(c);
            cReg[q] = c;
            __nv_bfloat16 hh = __float2bfloat16(h);
            HSw[(size_t)b * Hv + u0 + pj] = hh;
            if (seq) seq[((size_t)(t * Bv + b)) * Hv + u0 + pj] = h;
            if (a2) a2[((size_t)(t * Bv + b)) * Hv + u0 + pj] = hh;
            if (t == Tv - 1) g_h[b * Hv + u0 + pj] = h;
        }

        if (t < Tv - 1) {
            // xp prefetch for t+1 (independent of h) before the rendezvous
#pragma unroll
            for (int q = 0; q < 2; q++) {
                int b = pb0 + q * 32;
                const float* xr = xp + ((size_t)((t + 1) * Bv + b)) * Gv + u0 + pj;
#pragma unroll
                for (int g = 0; g < 4; g++) xv[q][g] = __ldg(xr + g * Hv);
            }
            __syncthreads();   // all block h-stores issued
            if (tid == 0) {
                // release-arrival: orders the block's prior stores without MEMBAR.ALL
                asm volatile("red.release.gpu.global.add.u32 [%0], 1;"
                             :: "l"(&g_barrier) : "memory");
                unsigned target = (unsigned)(t + 1) * (unsigned)gridDim.x;
                unsigned v;
                do {
                    asm volatile("ld.acquire.gpu.global.u32 %0, [%1];"
                                 : "=r"(v) : "l"(&g_barrier) : "memory");
                } while (v < target);
            }
            __syncthreads();
        }
    }
}

// ---------------- small FFMA2 sgemm (tiny GEMMs: m2, n_vec) ----------------
#define BKt 16
__global__ __launch_bounds__(128) void sgemm(
    const float* __restrict__ A, int lda,
    const float* __restrict__ B, int ldb,
    float* __restrict__ C, int ldc,
    int K, const float* __restrict__ bias1, int act)
{
    __shared__ __align__(16) float As[BKt][64 + 4];
    __shared__ __align__(16) float Bs[BKt][64 + 4];
    const int tid = threadIdx.x;
    const int nBase = blockIdx.x * 64;
    const long long mBase = (long long)blockIdx.y * 64;
    const int ty = tid >> 4, tx = tid & 15;

    float2 acc[8][2];
#pragma unroll
    for (int i = 0; i < 8; i++) { acc[i][0] = make_float2(0.f, 0.f); acc[i][1] = make_float2(0.f, 0.f); }

    for (int k0 = 0; k0 < K; k0 += BKt) {
#pragma unroll
        for (int i = 0; i < 2; i++) {
            int f = i * 128 + tid;
            int m = f >> 2, kq = f & 3;
            float4 va = *(const float4*)&A[(mBase + m) * (long long)lda + k0 + kq * 4];
            As[kq * 4 + 0][m] = va.x; As[kq * 4 + 1][m] = va.y;
            As[kq * 4 + 2][m] = va.z; As[kq * 4 + 3][m] = va.w;
            float4 vb = *(const float4*)&B[(long long)(nBase + m) * ldb + k0 + kq * 4];
            Bs[kq * 4 + 0][m] = vb.x; Bs[kq * 4 + 1][m] = vb.y;
            Bs[kq * 4 + 2][m] = vb.z; Bs[kq * 4 + 3][m] = vb.w;
        }
        __syncthreads();
#pragma unroll
        for (int kk = 0; kk < BKt; kk++) {
            float4 a0 = *(const float4*)&As[kk][ty * 8];
            float4 a1 = *(const float4*)&As[kk][ty * 8 + 4];
            float4 b4 = *(const float4*)&Bs[kk][tx * 4];
            float2 b01 = make_float2(b4.x, b4.y);
            float2 b23 = make_float2(b4.z, b4.w);
            float av[8] = {a0.x, a0.y, a0.z, a0.w, a1.x, a1.y, a1.z, a1.w};
#pragma unroll
            for (int i = 0; i < 8; i++) {
                float2 ad = make_float2(av[i], av[i]);
                acc[i][0] = ffma2(ad, b01, acc[i][0]);
                acc[i][1] = ffma2(ad, b23, acc[i][1]);
            }
        }
        __syncthreads();
    }

    float4 bb = make_float4(0.f, 0.f, 0.f, 0.f);
    if (bias1) bb = *(const float4*)&bias1[nBase + tx * 4];
#pragma unroll
    for (int i = 0; i < 8; i++) {
        long long m = mBase + ty * 8 + i;
        float4 r = make_float4(acc[i][0].x + bb.x, acc[i][0].y + bb.y,
                               acc[i][1].x + bb.z, acc[i][1].y + bb.w);
        if (act == 1) { r.x = tanhf_(r.x); r.y = tanhf_(r.y); r.z = tanhf_(r.z); r.w = tanhf_(r.w); }
        *(float4*)&C[m * (long long)ldc + nBase + tx * 4] = r;
    }
}

// ---------------- attention tail ----------------
__global__ void scores_k(const float* __restrict__ v) {
    int warp = (blockIdx.x * blockDim.x + threadIdx.x) >> 5;
    int lane = threadIdx.x & 31;
    if (warp >= Tv * Bv) return;
    int b = warp & 63;
    const float* m1 = g_m1 + (size_t)warp * Av;
    const float* m2 = g_m2 + b * Av;
    float s = 0.f;
    for (int a = lane; a < Av; a += 32) s += tanhf_(m1[a] + m2[a]) * v[a];
#pragma unroll
    for (int o = 16; o; o >>= 1) s += __shfl_xor_sync(0xffffffffu, s, o);
    if (!lane) g_sc[warp] = s;
}

__global__ void softmax_k() {
    int b = blockIdx.x;
    int t = threadIdx.x;
    __shared__ float red[Tv];
    float val = g_sc[t * Bv + b];
    red[t] = val; __syncthreads();
    for (int o = 128; o; o >>= 1) { if (t < o) red[t] = fmaxf(red[t], red[t + o]); __syncthreads(); }
    float mx = red[0]; __syncthreads();
    float e = __expf(val - mx);
    red[t] = e; __syncthreads();
    for (int o = 128; o; o >>= 1) { if (t < o) red[t] += red[t + o]; __syncthreads(); }
    g_sc[t * Bv + b] = __fdividef(e, red[0]);
}

// (b, h-range of 128) grid
__global__ void context_k() {
    int b = blockIdx.x;
    int h0 = blockIdx.y * 128;
    __shared__ float at[Tv];
    for (int t = threadIdx.x; t < Tv; t += blockDim.x) at[t] = g_sc[t * Bv + b];
    __syncthreads();
    int h = h0 + threadIdx.x;
    float s = 0.f;
#pragma unroll 4
    for (int t = 0; t < Tv; t++)
        s += g_seq1[((size_t)(t * Bv + b)) * Hv + h] * at[t];
    g_cat[b * 2 * Hv + h] = s;
    g_cat[b * 2 * Hv + Hv + h] = g_h[b * Hv + h];
}

__global__ void logit_k(const float* __restrict__ ow, const float* __restrict__ ob,
                        float* __restrict__ out) {
    int idx = blockIdx.x;
    int b = idx >> 1, c = idx & 1;
    int lane = threadIdx.x;
    float s = 0.f;
    for (int k = lane; k < Hv; k += 32) s += g_nvec[b * Hv + k] * ow[c * Hv + k];
#pragma unroll
    for (int o = 16; o; o >>= 1) s += __shfl_xor_sync(0xffffffffu, s, o);
    if (!lane) out[idx] = s + ob[c];
}

// ---------------- host orchestration ----------------
extern "C" void kernel_launch(void* const* d_in, const int* in_sizes, int n_in,
                              void* d_out, int out_size) {
    const int*   x      = (const int*)d_in[0];
    const float* embed_w= (const float*)d_in[1];
    const float* w_ih0  = (const float*)d_in[2];
    const float* w_hh0  = (const float*)d_in[3];
    const float* b_ih0  = (const float*)d_in[4];
    const float* b_hh0  = (const float*)d_in[5];
    const float* w_ih1  = (const float*)d_in[6];
    const float* w_hh1  = (const float*)d_in[7];
    const float* b_ih1  = (const float*)d_in[8];
    const float* b_hh1  = (const float*)d_in[9];
    const float* m1_w   = (const float*)d_in[10];
    const float* m1_b   = (const float*)d_in[11];
    const float* m2_w   = (const float*)d_in[12];
    const float* m2_b   = (const float*)d_in[13];
    const float* vv     = (const float*)d_in[14];
    const float* n_w    = (const float*)d_in[15];
    const float* n_b    = (const float*)d_in[16];
    const float* out_w  = (const float*)d_in[17];
    const float* out_b  = (const float*)d_in[18];
    float* out = (float*)d_out;

    cudaFuncSetAttribute(lstm_scan_mma, cudaFuncAttributeMaxDynamicSharedMemorySize, SCAN_SMEM);
    cudaFuncSetAttribute(mma_gemm, cudaFuncAttributeMaxDynamicSharedMemorySize, GEMM_SMEM);

    __nv_bfloat16 *p_A2, *p_B2, *p_WS;
    float *p_xp, *p_seq1, *p_h, *p_m1, *p_m2, *p_cat, *p_nvec;
    cudaGetSymbolAddress((void**)&p_A2,   g_A2);
    cudaGetSymbolAddress((void**)&p_B2,   g_B2);
    cudaGetSymbolAddress((void**)&p_WS,   g_WS);
    cudaGetSymbolAddress((void**)&p_xp,   g_xp);
    cudaGetSymbolAddress((void**)&p_seq1, g_seq1);
    cudaGetSymbolAddress((void**)&p_h,    g_h);
    cudaGetSymbolAddress((void**)&p_m1,   g_m1);
    cudaGetSymbolAddress((void**)&p_m2,   g_m2);
    cudaGetSymbolAddress((void**)&p_cat,  g_cat);
    cudaGetSymbolAddress((void**)&p_nvec, g_nvec);

    // ---- layer 0 ----
    gather_pack<<<Tv * Bv, 128>>>(x, embed_w);
    pack_B<<<(Gv * Ev + 255) / 256, 256>>>(w_ih0, Gv, Ev);
    mma_gemm<<<dim3(Gv / 128, (Tv * Bv) / 128), 256, GEMM_SMEM>>>(p_A2, p_B2, p_xp, Gv,
                                                                  Ev, b_ih0, b_hh0);
    pack_WS<<<(Gv * Hv + 255) / 256, 256>>>(w_hh0);
    zero_state<<<256, 256>>>();
    lstm_scan_mma<<<SCAN_BLOCKS, 256, SCAN_SMEM>>>(p_WS, p_xp, nullptr, p_A2);

    // ---- layer 1 ----
    pack_B<<<(Gv * Hv + 255) / 256, 256>>>(w_ih1, Gv, Hv);
    mma_gemm<<<dim3(Gv / 128, (Tv * Bv) / 128), 256, GEMM_SMEM>>>(p_A2, p_B2, p_xp, Gv,
                                                                  Hv, b_ih1, b_hh1);
    pack_WS<<<(Gv * Hv + 255) / 256, 256>>>(w_hh1);
    zero_state<<<256, 256>>>();
    lstm_scan_mma<<<SCAN_BLOCKS, 256, SCAN_SMEM>>>(p_WS, p_xp, p_seq1, p_A2);

    // ---- attention ----
    pack_B<<<(Av * Hv + 255) / 256, 256>>>(m1_w, Av, Hv);
    mma_gemm<<<dim3(Av / 128, (Tv * Bv) / 128), 256, GEMM_SMEM>>>(p_A2, p_B2, p_m1, Av,
                                                                  Hv, m1_b, nullptr);
    sgemm<<<dim3(Av / 64, 1), 128>>>(p_h, Hv, m2_w, Hv, p_m2, Av, Hv, m2_b, 0);
    scores_k<<<(Tv * Bv * 32) / 256, 256>>>(vv);
    softmax_k<<<Bv, Tv>>>();
    context_k<<<dim3(Bv, Hv / 128), 128>>>();
    sgemm<<<dim3(Hv / 64, 1), 128>>>(p_cat, 2 * Hv, n_w, 2 * Hv, p_nvec, Hv, 2 * Hv, n_b, 1);
    logit_k<<<Bv * Cv, 32>>>(out_w, out_b, out);
}

// round 13
// speedup vs baseline: 1.2414x; 1.0174x over previous
#include <cuda_runtime.h>
#include <cuda_bf16.h>
#include <cstdint>
#include <math.h>

#define Bv 64
#define Tv 256
#define Hv 1024
#define Ev 512
#define Av 512
#define Gv 4096   /* 4*H */
#define Cv 2
#define SCAN_BLOCKS 128
#define BH (Bv * Hv)

#define WSLICE 65536               /* 32 rows * 1024 bf16 * 2B */
#define ABUF 32768                 /* 64 rows * 256 bf16 * 2B  */
#define SCAN_SMEM (WSLICE + 4 * ABUF)   /* 196608 */
#define GEMM_SMEM 49152            /* 3-stage: 3*(8K A + 8K B) */

// ---------------- scratch (static device globals; no allocations) ----------------
__device__ __nv_bfloat16 g_A2[(size_t)Tv * Bv * Hv];       // bf16 A / bf16 h-sequence
__device__ __nv_bfloat16 g_B2[(size_t)Gv * Hv];            // bf16 B
__device__ __nv_bfloat16 g_WS[(size_t)Gv * Hv];            // per-block swizzled W_hh slices
__device__ __nv_bfloat16 g_HS[2 * 64 * Hv];                // h bf16, double-buffered
__device__ float g_xp  [(size_t)Tv * Bv * Gv];             // scan-blocked: [t][bi][b][32]
__device__ float g_h   [BH];
__device__ float g_m1  [(size_t)Tv * Bv * Av];
__device__ float g_m2  [Bv * Av];
__device__ float g_sc  [Tv * Bv];
__device__ float g_cat [Bv * 2 * Hv];
__device__ float g_nvec[Bv * Hv];
__device__ unsigned g_barrier;

// ---------------- helpers ----------------
__device__ __forceinline__ uint32_t smem_u32(const void* p) {
    uint32_t a;
    asm("{ .reg .u64 t; cvta.to.shared.u64 t, %1; cvt.u32.u64 %0, t; }" : "=r"(a) : "l"(p));
    return a;
}
__device__ __forceinline__ void cp16(uint32_t s, const void* g) {
    asm volatile("cp.async.cg.shared.global [%0], [%1], 16;" :: "r"(s), "l"(g));
}
#define CP_COMMIT() asm volatile("cp.async.commit_group;" ::: "memory")
#define CP_WAIT(n)  asm volatile("cp.async.wait_group %0;" :: "n"(n) : "memory")

__device__ __forceinline__ void ldm_x4(uint32_t* r, uint32_t addr) {
    asm volatile("ldmatrix.sync.aligned.m8n8.x4.shared.b16 {%0,%1,%2,%3}, [%4];"
        : "=r"(r[0]), "=r"(r[1]), "=r"(r[2]), "=r"(r[3]) : "r"(addr));
}
__device__ __forceinline__ void mma16816(float* c, const uint32_t* a, uint32_t b0, uint32_t b1) {
    asm volatile("mma.sync.aligned.m16n8k16.row.col.f32.bf16.bf16.f32 "
        "{%0,%1,%2,%3}, {%4,%5,%6,%7}, {%8,%9}, {%0,%1,%2,%3};"
        : "+f"(c[0]), "+f"(c[1]), "+f"(c[2]), "+f"(c[3])
        : "r"(a[0]), "r"(a[1]), "r"(a[2]), "r"(a[3]), "r"(b0), "r"(b1));
}

union f2u { float2 f; unsigned long long u; };
__device__ __forceinline__ float2 ffma2(float2 a, float2 b, float2 c) {
    f2u A, B, C, D; A.f = a; B.f = b; C.f = c;
    asm("fma.rn.f32x2 %0, %1, %2, %3;" : "=l"(D.u) : "l"(A.u), "l"(B.u), "l"(C.u));
    return D.f;
}

// fast transcendentals (validated R12: rel_err impact negligible)
__device__ __forceinline__ float sigmoidf_(float x) {
    return __fdividef(1.f, 1.f + __expf(-x));
}
__device__ __forceinline__ float tanhf_(float x) {
    x = fminf(15.f, fmaxf(-15.f, x));
    float e = __expf(2.f * x);
    return __fdividef(e - 1.f, e + 1.f);
}

// XOR swizzle for 64B-row tiles: conflict-free ldmatrix (validated R5-R12)
__device__ __host__ __forceinline__ uint32_t sw_off(int r, int kq) {
    return (uint32_t)(r * 64 + ((kq ^ ((r >> 1) & 3)) << 4));
}

// ================= mma.sync bf16 GEMM, 3-stage pipeline =================
// mode 0: row-major C (ldc). mode 1: scan-blocked xp2 [t][bi][b][32] (C = xp2 base).
__global__ __launch_bounds__(256) void mma_gemm(
    const __nv_bfloat16* __restrict__ A2, const __nv_bfloat16* __restrict__ B2,
    float* __restrict__ C, int ldc, int K3,
    const float* __restrict__ bias1, const float* __restrict__ bias2, int mode)
{
    extern __shared__ __align__(128) char gsm[];
    const uint32_t uA = smem_u32(gsm);            // 3 x 8192
    const uint32_t uB = uA + 24576;               // 3 x 8192

    const int tid = threadIdx.x, wid = tid >> 5, lid = tid & 31;
    const int wm = wid >> 1, wn = wid & 1;
    const long long mBase = (long long)blockIdx.y * 128;
    const int nBase = blockIdx.x * 128;

    const __nv_bfloat16* Ag = A2 + mBase * (size_t)K3;
    const __nv_bfloat16* Bg = B2 + (size_t)nBase * K3;

    float acc[2][8][4];
#pragma unroll
    for (int i = 0; i < 2; i++)
#pragma unroll
        for (int j = 0; j < 8; j++)
#pragma unroll
            for (int q = 0; q < 4; q++) acc[i][j][q] = 0.f;

    const int NS = K3 / 32;
    const int c0r = (tid * 2) >> 2,     c0q = (tid * 2) & 3;
    const int c1r = (tid * 2 + 1) >> 2, c1q = (tid * 2 + 1) & 3;

    const int aR = ((lid >> 3) & 1) * 8 + (lid & 7);
    const int aQ = (lid >> 4) & 1;
    const int bR = ((lid >> 4) & 1) * 8 + (lid & 7);
    const int bQ = (lid >> 3) & 1;

#pragma unroll
    for (int ps = 0; ps < 2; ps++) {
        const int k0 = ps * 32;
        uint32_t dA = uA + ps * 8192, dB = uB + ps * 8192;
        cp16(dA + sw_off(c0r, c0q), Ag + (size_t)c0r * K3 + k0 + c0q * 8);
        cp16(dA + sw_off(c1r, c1q), Ag + (size_t)c1r * K3 + k0 + c1q * 8);
        cp16(dB + sw_off(c0r, c0q), Bg + (size_t)c0r * K3 + k0 + c0q * 8);
        cp16(dB + sw_off(c1r, c1q), Bg + (size_t)c1r * K3 + k0 + c1q * 8);
        CP_COMMIT();
    }

    int buf = 0, pbuf = 2;
    for (int s = 0; s < NS; s++) {
        if (s + 2 < NS) {
            const int k0 = (s + 2) * 32;
            uint32_t dA = uA + pbuf * 8192, dB = uB + pbuf * 8192;
            cp16(dA + sw_off(c0r, c0q), Ag + (size_t)c0r * K3 + k0 + c0q * 8);
            cp16(dA + sw_off(c1r, c1q), Ag + (size_t)c1r * K3 + k0 + c1q * 8);
            cp16(dB + sw_off(c0r, c0q), Bg + (size_t)c0r * K3 + k0 + c0q * 8);
            cp16(dB + sw_off(c1r, c1q), Bg + (size_t)c1r * K3 + k0 + c1q * 8);
        }
        CP_COMMIT();
        CP_WAIT(2);
        __syncthreads();

        const uint32_t bufA = uA + buf * 8192;
        const uint32_t bufB = uB + buf * 8192;
#pragma unroll
        for (int kk8 = 0; kk8 < 4; kk8 += 2) {
            uint32_t a[2][4];
#pragma unroll
            for (int fm = 0; fm < 2; fm++) {
                int r = wm * 32 + fm * 16 + aR;
                ldm_x4(a[fm], bufA + sw_off(r, kk8 + aQ));
            }
#pragma unroll
            for (int jp = 0; jp < 4; jp++) {
                uint32_t b[4];
                int r = wn * 64 + jp * 16 + bR;
                ldm_x4(b, bufB + sw_off(r, kk8 + bQ));
#pragma unroll
                for (int fm = 0; fm < 2; fm++) {
                    mma16816(acc[fm][2 * jp],     a[fm], b[0], b[1]);
                    mma16816(acc[fm][2 * jp + 1], a[fm], b[2], b[3]);
                }
            }
        }
        __syncthreads();
        buf = (buf == 2) ? 0 : buf + 1;
        pbuf = (pbuf == 2) ? 0 : pbuf + 1;
    }

    const int gid = lid >> 2, tig = lid & 3;
#pragma unroll
    for (int fm = 0; fm < 2; fm++) {
#pragma unroll
        for (int j = 0; j < 8; j++) {
            int n = nBase + wn * 64 + j * 8 + tig * 2;
            float b0 = 0.f, b1 = 0.f;
            if (bias1) { b0 = bias1[n]; b1 = bias1[n + 1]; }
            if (bias2) { b0 += bias2[n]; b1 += bias2[n + 1]; }
            long long m0 = mBase + wm * 32 + fm * 16 + gid;
            if (mode == 0) {
                float* r0 = C + m0 * (long long)ldc + n;
                r0[0] = acc[fm][j][0] + b0;
                r0[1] = acc[fm][j][1] + b1;
                float* r1 = r0 + 8LL * ldc;
                r1[0] = acc[fm][j][2] + b0;
                r1[1] = acc[fm][j][3] + b1;
            } else {
                // scan-blocked: [t][bi][b][32], idx32 = g*8 + jj
                int t = (int)(m0 >> 6), b = (int)(m0 & 63);
                int g = n >> 10, u = n & 1023;
                size_t base = (((size_t)(t * 128 + (u >> 3))) * 64 + b) * 32
                              + (g << 3) + (u & 7);
                C[base]          = acc[fm][j][0] + b0;
                C[base + 1]      = acc[fm][j][1] + b1;
                C[base + 8 * 32]     = acc[fm][j][2] + b0;   // row m0+8 -> b+8 (<=63)
                C[base + 8 * 32 + 1] = acc[fm][j][3] + b1;
            }
        }
    }
}

// ---------------- packing kernels ----------------
__global__ void pack_B(const float* __restrict__ W, int N, int K) {
    int i = blockIdx.x * blockDim.x + threadIdx.x;
    if (i >= N * K) return;
    g_B2[(size_t)i] = __float2bfloat16(W[i]);
}

// scan weights: per-block (128 blocks x 8 units) pre-swizzled smem image (R8 layout)
__global__ void pack_WS(const float* __restrict__ W) {
    int i = blockIdx.x * blockDim.x + threadIdx.x;   // over Gv*Hv
    if (i >= Gv * Hv) return;
    int n = i >> 10, k = i & 1023;
    __nv_bfloat16 hi = __float2bfloat16(W[i]);
    int g = n >> 10, bi = (n & 1023) >> 3, j = n & 7;
    int r = g * 8 + j;
    char* base = (char*)g_WS + (size_t)bi * WSLICE;
    *(__nv_bfloat16*)(base + (size_t)(k >> 5) * 2048
                      + sw_off(r, (k >> 3) & 3) + (k & 7) * 2) = hi;
}

// embedding gather into A2 bf16, row stride Ev
__global__ void gather_pack(const int* __restrict__ x, const float* __restrict__ ew) {
    int m = blockIdx.x;            // t*B + b
    int b = m & 63, t = m >> 6;
    int row = x[b * Tv + t];
    const float* src = ew + (size_t)row * Ev;
    __nv_bfloat16* dst = g_A2 + (size_t)m * Ev;
    for (int k = threadIdx.x; k < Ev; k += blockDim.x)
        dst[k] = __float2bfloat16(src[k]);
}

__global__ void zero_state() {
    int i = blockIdx.x * blockDim.x + threadIdx.x;
    if (i < BH) g_h[i] = 0.f;
    if (i == 0) g_barrier = 0u;
}

// ---------------- persistent LSTM scan on tensor cores (R12 structure) ----------------
// 128 blocks x 256 threads. Block bi owns units u0=bi*8 -> 32 gate rows. W slice (64KB)
// smem-resident. xp in scan-blocked layout: 8KB dense read per block-step.
__global__ __launch_bounds__(256) void lstm_scan_mma(
    const __nv_bfloat16* __restrict__ WS,
    const float* __restrict__ xp2,      // [t][bi][b][32]
    __nv_bfloat16* __restrict__ a2)     // bf16 seq out, stride Hv
{
    extern __shared__ __align__(128) char sm[];
    const int tid = threadIdx.x, wid = tid >> 5, lid = tid & 31;
    const int wm = wid >> 1, wn = wid & 1;
    const int bi = blockIdx.x, u0 = bi * 8;
    const uint32_t sW = smem_u32(sm);
    const uint32_t sA = sW + WSLICE;
    float* Cs = (float*)(sm + WSLICE);   // overlays A buffers (disjoint in time)

    const int aR = ((lid >> 3) & 1) * 8 + (lid & 7);
    const int aQ = (lid >> 4) & 1;
    const int bR = ((lid >> 4) & 1) * 8 + (lid & 7);
    const int bQ = (lid >> 3) & 1;
    const int gid = lid >> 2, tig = lid & 3;

    // load W slice (64KB) once
    {
        const char* wg = (const char*)WS + (size_t)bi * WSLICE;
        for (int i = tid; i < WSLICE / 16; i += 256)
            cp16(sW + (uint32_t)(i * 16), wg + (size_t)i * 16);
        CP_COMMIT(); CP_WAIT(0);
        __syncthreads();
    }

    const int pb0 = tid >> 3, pj = tid & 7;
    const float* xbase = xp2 + (size_t)bi * (64 * 32);   // + t*128*64*32

    float cReg[2] = {0.f, 0.f};

    // xp prefetch for t=0 (dense: thread (b,pj) reads 4 floats at stride 8 in its 128B row)
    float xv[2][4];
#pragma unroll
    for (int q = 0; q < 2; q++) {
        int b = pb0 + q * 32;
        const float* xr = xbase + b * 32 + pj;
#pragma unroll
        for (int g = 0; g < 4; g++) xv[q][g] = __ldg(xr + g * 8);
    }

    for (int t = 0; t < Tv; t++) {
        if (t > 0) {
            const __nv_bfloat16* HS = g_HS + (size_t)(t & 1) * (64 * Hv);
            float acc[2][4];
#pragma unroll
            for (int j = 0; j < 2; j++)
#pragma unroll
                for (int q = 0; q < 4; q++) acc[j][q] = 0.f;

            // prefetch stages 0..2 (BK=256, 32KB each; 8 cp16/thread)
#pragma unroll
            for (int s = 0; s < 3; s++) {
                int k0 = s * 256;
#pragma unroll
                for (int q = 0; q < 8; q++) {
                    int id = tid + q * 256;
                    int r = id >> 5, c16 = id & 31;
                    cp16(sA + s * ABUF + (c16 >> 2) * 4096 + sw_off(r, c16 & 3),
                         HS + (size_t)r * Hv + k0 + c16 * 8);
                }
                CP_COMMIT();
            }

#pragma unroll 1
            for (int s = 0; s < 4; s++) {
                CP_WAIT(2);
                __syncthreads();
                const uint32_t bufA = sA + (s & 3) * ABUF;
                const uint32_t bufW = sW + (uint32_t)s * 16384;
#pragma unroll
                for (int sub = 0; sub < 8; sub++) {
#pragma unroll
                    for (int kk8 = 0; kk8 < 4; kk8 += 2) {
                        uint32_t a[4], b[4];
                        ldm_x4(a, bufA + sub * 4096 + sw_off(wm * 16 + aR, kk8 + aQ));
                        ldm_x4(b, bufW + sub * 2048 + sw_off(wn * 16 + bR, kk8 + bQ));
                        mma16816(acc[0], a, b[0], b[1]);
                        mma16816(acc[1], a, b[2], b[3]);
                    }
                }
                if (s + 3 < 4) {
                    int k0 = (s + 3) * 256;
                    uint32_t d = sA + ((s + 3) & 3) * ABUF;
#pragma unroll
                    for (int q = 0; q < 8; q++) {
                        int id = tid + q * 256;
                        int r = id >> 5, c16 = id & 31;
                        cp16(d + (c16 >> 2) * 4096 + sw_off(r, c16 & 3),
                             HS + (size_t)r * Hv + k0 + c16 * 8);
                    }
                }
                CP_COMMIT();
            }
            __syncthreads();             // A buffers idle -> Cs overlay

#pragma unroll
            for (int j = 0; j < 2; j++) {
                int n = wn * 16 + j * 8 + tig * 2;
                int b0 = wm * 16 + gid;
                Cs[b0 * 33 + n]           = acc[j][0];
                Cs[b0 * 33 + n + 1]       = acc[j][1];
                Cs[(b0 + 8) * 33 + n]     = acc[j][2];
                Cs[(b0 + 8) * 33 + n + 1] = acc[j][3];
            }
            __syncthreads();
        }

        __nv_bfloat16* HSw = g_HS + (size_t)((t + 1) & 1) * (64 * Hv);
#pragma unroll
        for (int q = 0; q < 2; q++) {
            int b = pb0 + q * 32;
            float gi = xv[q][0], gf = xv[q][1], gg = xv[q][2], go = xv[q][3];
            if (t > 0) {
                gi += Cs[b * 33 + pj];
                gf += Cs[b * 33 + 8 + pj];
                gg += Cs[b * 33 + 16 + pj];
                go += Cs[b * 33 + 24 + pj];
            }
            float c = sigmoidf_(gf) * cReg[q] + sigmoidf_(gi) * tanhf_(gg);
            float h = sigmoidf_(go) * tanhf_(c);
            cReg[q] = c;
            __nv_bfloat16 hh = __float2bfloat16(h);
            HSw[(size_t)b * Hv + u0 + pj] = hh;
            a2[((size_t)(t * Bv + b)) * Hv + u0 + pj] = hh;
            if (t == Tv - 1) g_h[b * Hv + u0 + pj] = h;
        }

        if (t < Tv - 1) {
            // dense xp prefetch for t+1 before the rendezvous
            const float* xn = xbase + (size_t)(t + 1) * (128 * 64 * 32);
#pragma unroll
            for (int q = 0; q < 2; q++) {
                int b = pb0 + q * 32;
                const float* xr = xn + b * 32 + pj;
#pragma unroll
                for (int g = 0; g < 4; g++) xv[q][g] = __ldg(xr + g * 8);
            }
            __syncthreads();
            if (tid == 0) {
                asm volatile("red.release.gpu.global.add.u32 [%0], 1;"
                             :: "l"(&g_barrier) : "memory");
                unsigned target = (unsigned)(t + 1) * (unsigned)gridDim.x;
                unsigned v;
                do {
                    asm volatile("ld.acquire.gpu.global.u32 %0, [%1];"
                                 : "=r"(v) : "l"(&g_barrier) : "memory");
                } while (v < target);
            }
            __syncthreads();
        }
    }
}

// ---------------- small FFMA2 sgemm (tiny GEMMs: m2, n_vec) ----------------
#define BKt 16
__global__ __launch_bounds__(128) void sgemm(
    const float* __restrict__ A, int lda,
    const float* __restrict__ B, int ldb,
    float* __restrict__ C, int ldc,
    int K, const float* __restrict__ bias1, int act)
{
    __shared__ __align__(16) float As[BKt][64 + 4];
    __shared__ __align__(16) float Bs[BKt][64 + 4];
    const int tid = threadIdx.x;
    const int nBase = blockIdx.x * 64;
    const long long mBase = (long long)blockIdx.y * 64;
    const int ty = tid >> 4, tx = tid & 15;

    float2 acc[8][2];
#pragma unroll
    for (int i = 0; i < 8; i++) { acc[i][0] = make_float2(0.f, 0.f); acc[i][1] = make_float2(0.f, 0.f); }

    for (int k0 = 0; k0 < K; k0 += BKt) {
#pragma unroll
        for (int i = 0; i < 2; i++) {
            int f = i * 128 + tid;
            int m = f >> 2, kq = f & 3;
            float4 va = *(const float4*)&A[(mBase + m) * (long long)lda + k0 + kq * 4];
            As[kq * 4 + 0][m] = va.x; As[kq * 4 + 1][m] = va.y;
            As[kq * 4 + 2][m] = va.z; As[kq * 4 + 3][m] = va.w;
            float4 vb = *(const float4*)&B[(long long)(nBase + m) * ldb + k0 + kq * 4];
            Bs[kq * 4 + 0][m] = vb.x; Bs[kq * 4 + 1][m] = vb.y;
            Bs[kq * 4 + 2][m] = vb.z; Bs[kq * 4 + 3][m] = vb.w;
        }
        __syncthreads();
#pragma unroll
        for (int kk = 0; kk < BKt; kk++) {
            float4 a0 = *(const float4*)&As[kk][ty * 8];
            float4 a1 = *(const float4*)&As[kk][ty * 8 + 4];
            float4 b4 = *(const float4*)&Bs[kk][tx * 4];
            float2 b01 = make_float2(b4.x, b4.y);
            float2 b23 = make_float2(b4.z, b4.w);
            float av[8] = {a0.x, a0.y, a0.z, a0.w, a1.x, a1.y, a1.z, a1.w};
#pragma unroll
            for (int i = 0; i < 8; i++) {
                float2 ad = make_float2(av[i], av[i]);
                acc[i][0] = ffma2(ad, b01, acc[i][0]);
                acc[i][1] = ffma2(ad, b23, acc[i][1]);
            }
        }
        __syncthreads();
    }

    float4 bb = make_float4(0.f, 0.f, 0.f, 0.f);
    if (bias1) bb = *(const float4*)&bias1[nBase + tx * 4];
#pragma unroll
    for (int i = 0; i < 8; i++) {
        long long m = mBase + ty * 8 + i;
        float4 r = make_float4(acc[i][0].x + bb.x, acc[i][0].y + bb.y,
                               acc[i][1].x + bb.z, acc[i][1].y + bb.w);
        if (act == 1) { r.x = tanhf_(r.x); r.y = tanhf_(r.y); r.z = tanhf_(r.z); r.w = tanhf_(r.w); }
        *(float4*)&C[m * (long long)ldc + nBase + tx * 4] = r;
    }
}

// ---------------- attention tail ----------------
__global__ void scores_k(const float* __restrict__ v) {
    int warp = (blockIdx.x * blockDim.x + threadIdx.x) >> 5;
    int lane = threadIdx.x & 31;
    if (warp >= Tv * Bv) return;
    int b = warp & 63;
    const float* m1 = g_m1 + (size_t)warp * Av;
    const float* m2 = g_m2 + b * Av;
    float s = 0.f;
    for (int a = lane; a < Av; a += 32) s += tanhf_(m1[a] + m2[a]) * v[a];
#pragma unroll
    for (int o = 16; o; o >>= 1) s += __shfl_xor_sync(0xffffffffu, s, o);
    if (!lane) g_sc[warp] = s;
}

__global__ void softmax_k() {
    int b = blockIdx.x;
    int t = threadIdx.x;
    __shared__ float red[Tv];
    float val = g_sc[t * Bv + b];
    red[t] = val; __syncthreads();
    for (int o = 128; o; o >>= 1) { if (t < o) red[t] = fmaxf(red[t], red[t + o]); __syncthreads(); }
    float mx = red[0]; __syncthreads();
    float e = __expf(val - mx);
    red[t] = e; __syncthreads();
    for (int o = 128; o; o >>= 1) { if (t < o) red[t] += red[t + o]; __syncthreads(); }
    g_sc[t * Bv + b] = __fdividef(e, red[0]);
}

// context over bf16 sequence in g_A2; (b, h-range of 128) grid
__global__ void context_k() {
    int b = blockIdx.x;
    int h0 = blockIdx.y * 128;
    __shared__ float at[Tv];
    for (int t = threadIdx.x; t < Tv; t += blockDim.x) at[t] = g_sc[t * Bv + b];
    __syncthreads();
    int h = h0 + threadIdx.x;
    float s = 0.f;
#pragma unroll 4
    for (int t = 0; t < Tv; t++)
        s += __bfloat162float(g_A2[((size_t)(t * Bv + b)) * Hv + h]) * at[t];
    g_cat[b * 2 * Hv + h] = s;
    g_cat[b * 2 * Hv + Hv + h] = g_h[b * Hv + h];
}

__global__ void logit_k(const float* __restrict__ ow, const float* __restrict__ ob,
                        float* __restrict__ out) {
    int idx = blockIdx.x;
    int b = idx >> 1, c = idx & 1;
    int lane = threadIdx.x;
    float s = 0.f;
    for (int k = lane; k < Hv; k += 32) s += g_nvec[b * Hv + k] * ow[c * Hv + k];
#pragma unroll
    for (int o = 16; o; o >>= 1) s += __shfl_xor_sync(0xffffffffu, s, o);
    if (!lane) out[idx] = s + ob[c];
}

// ---------------- host orchestration ----------------
extern "C" void kernel_launch(void* const* d_in, const int* in_sizes, int n_in,
                              void* d_out, int out_size) {
    const int*   x      = (const int*)d_in[0];
    const float* embed_w= (const float*)d_in[1];
    const float* w_ih0  = (const float*)d_in[2];
    const float* w_hh0  = (const float*)d_in[3];
    const float* b_ih0  = (const float*)d_in[4];
    const float* b_hh0  = (const float*)d_in[5];
    const float* w_ih1  = (const float*)d_in[6];
    const float* w_hh1  = (const float*)d_in[7];
    const float* b_ih1  = (const float*)d_in[8];
    const float* b_hh1  = (const float*)d_in[9];
    const float* m1_w   = (const float*)d_in[10];
    const float* m1_b   = (const float*)d_in[11];
    const float* m2_w   = (const float*)d_in[12];
    const float* m2_b   = (const float*)d_in[13];
    const float* vv     = (const float*)d_in[14];
    const float* n_w    = (const float*)d_in[15];
    const float* n_b    = (const float*)d_in[16];
    const float* out_w  = (const float*)d_in[17];
    const float* out_b  = (const float*)d_in[18];
    float* out = (float*)d_out;

    cudaFuncSetAttribute(lstm_scan_mma, cudaFuncAttributeMaxDynamicSharedMemorySize, SCAN_SMEM);
    cudaFuncSetAttribute(mma_gemm, cudaFuncAttributeMaxDynamicSharedMemorySize, GEMM_SMEM);

    __nv_bfloat16 *p_A2, *p_B2, *p_WS;
    float *p_xp, *p_h, *p_m1, *p_m2, *p_cat, *p_nvec;
    cudaGetSymbolAddress((void**)&p_A2,   g_A2);
    cudaGetSymbolAddress((void**)&p_B2,   g_B2);
    cudaGetSymbolAddress((void**)&p_WS,   g_WS);
    cudaGetSymbolAddress((void**)&p_xp,   g_xp);
    cudaGetSymbolAddress((void**)&p_h,    g_h);
    cudaGetSymbolAddress((void**)&p_m1,   g_m1);
    cudaGetSymbolAddress((void**)&p_m2,   g_m2);
    cudaGetSymbolAddress((void**)&p_cat,  g_cat);
    cudaGetSymbolAddress((void**)&p_nvec, g_nvec);

    // ---- layer 0 ----
    gather_pack<<<Tv * Bv, 128>>>(x, embed_w);
    pack_B<<<(Gv * Ev + 255) / 256, 256>>>(w_ih0, Gv, Ev);
    mma_gemm<<<dim3(Gv / 128, (Tv * Bv) / 128), 256, GEMM_SMEM>>>(p_A2, p_B2, p_xp, 0,
                                                                  Ev, b_ih0, b_hh0, 1);
    pack_WS<<<(Gv * Hv + 255) / 256, 256>>>(w_hh0);
    zero_state<<<256, 256>>>();
    lstm_scan_mma<<<SCAN_BLOCKS, 256, SCAN_SMEM>>>(p_WS, p_xp, p_A2);

    // ---- layer 1 ----
    pack_B<<<(Gv * Hv + 255) / 256, 256>>>(w_ih1, Gv, Hv);
    mma_gemm<<<dim3(Gv / 128, (Tv * Bv) / 128), 256, GEMM_SMEM>>>(p_A2, p_B2, p_xp, 0,
                                                                  Hv, b_ih1, b_hh1, 1);
    pack_WS<<<(Gv * Hv + 255) / 256, 256>>>(w_hh1);
    zero_state<<<256, 256>>>();
    lstm_scan_mma<<<SCAN_BLOCKS, 256, SCAN_SMEM>>>(p_WS, p_xp, p_A2);

    // ---- attention ----
    pack_B<<<(Av * Hv + 255) / 256, 256>>>(m1_w, Av, Hv);
    mma_gemm<<<dim3(Av / 128, (Tv * Bv) / 128), 256, GEMM_SMEM>>>(p_A2, p_B2, p_m1, Av,
                                                                  Hv, m1_b, nullptr, 0);
    sgemm<<<dim3(Av / 64, 1), 128>>>(p_h, Hv, m2_w, Hv, p_m2, Av, Hv, m2_b, 0);
    scores_k<<<(Tv * Bv * 32) / 256, 256>>>(vv);
    softmax_k<<<Bv, Tv>>>();
    context_k<<<dim3(Bv, Hv / 128), 128>>>();
    sgemm<<<dim3(Hv / 64, 1), 128>>>(p_cat, 2 * Hv, n_w, 2 * Hv, p_nvec, Hv, 2 * Hv, n_b, 1);
    logit_k<<<Bv * Cv, 32>>>(out_w, out_b, out);
}